// round 1
// baseline (speedup 1.0000x reference)
#include <cuda_runtime.h>
#include <cuda_bf16.h>
#include <math.h>

// ---------------- constants ----------------
#define BB   16
#define NN_  512
#define LL   1024
#define CD   128     // comp_dim
#define GD   64      // gat_dim
#define NH   4       // heads
#define LAT  128

// ---------------- scratch (device globals; no allocs allowed) ----------------
__device__ float g_av       [BB*NN_*CD];      // atom embeddings
__device__ float g_wh1      [BB*NN_*(GD*NH)]; // per-head Wh, packed cols h*64+f
__device__ float g_multi    [BB*NN_*(GD*NH)];
__device__ float g_wh2      [BB*NN_*CD];
__device__ float g_x        [BB*NN_*CD];
__device__ float g_atoms_vec[BB*NN_*LAT];
__device__ float g_av_att   [BB*NN_*LAT];
__device__ float g_src1[BB*NH*NN_], g_dst1[BB*NH*NN_];
__device__ float g_src2[BB*NN_],    g_dst2[BB*NN_];
__device__ float g_cnvA[BB*LL*CD];
__device__ float g_cnvB[BB*LL*CD];
__device__ float g_T[30*11*CD];               // per-amino-id row-conv table (layer 1)
__device__ float g_Wcat  [CD*(GD*NH)];        // packed W_gat -> (128,256)
__device__ float g_WcompT[CD*LAT];
__device__ float g_WattT [LAT*LAT];
__device__ float g_comp[BB*LAT], g_prot[BB*LAT];

__device__ __forceinline__ float lrelu(float x){ return x > 0.f ? x : 0.2f*x; }
__device__ __forceinline__ float eluf (float x){ return x > 0.f ? x : (__expf(x) - 1.f); }

// ---------------- tiny prep kernels ----------------
__global__ void k_pack_wgat(const float* __restrict__ W_gat){
    // Wcat[k][h*64+f] = W_gat[h][k][f]
    int k = blockIdx.x;            // 0..127
    int c = threadIdx.x;           // 0..255
    int h = c >> 6, f = c & 63;
    g_Wcat[k*256 + c] = W_gat[((h*128) + k)*64 + f];
}

__global__ void k_transp128(const float* __restrict__ in, float* __restrict__ out){
    // out[k][c] = in[c][k], 128x128
    int k = blockIdx.x, c = threadIdx.x;
    out[k*128 + c] = in[c*128 + k];
}

__global__ void k_table(const float* __restrict__ conv_w, const float* __restrict__ E_amino){
    // T[a][dl][f] = sum_df w0[dl][df] * E_amino[a][f+df-5]
    int dl = blockIdx.x;           // 0..10
    int a  = blockIdx.y;           // 0..29
    int f  = threadIdx.x;          // 0..127
    float acc = 0.f;
    #pragma unroll
    for (int df = 0; df < 11; ++df) {
        int fi = f + df - 5;
        if (fi >= 0 && fi < 128) acc += conv_w[dl*11 + df] * E_amino[a*128 + fi];
    }
    g_T[(a*11 + dl)*128 + f] = acc;
}

__global__ void k_embed_atoms(const int* __restrict__ atoms, const float* __restrict__ E_atom){
    int row = blockIdx.x;          // 0..8191
    int f   = threadIdx.x;         // 0..127
    g_av[(size_t)row*128 + f] = E_atom[atoms[row]*128 + f];
}

// ---------------- generic tiled fp32 GEMM: C = act(A@B + bias) ----------------
// grid: (M/64, N/64), block 256. act: 0 none, 1 leaky
__global__ void __launch_bounds__(256) k_gemm(
    const float* __restrict__ A, const float* __restrict__ B,
    const float* __restrict__ bias, float* __restrict__ C,
    int M, int N, int K, int act)
{
    __shared__ float As[64][17];
    __shared__ float Bs[16][68];
    const int m0 = blockIdx.x*64, n0 = blockIdx.y*64;
    const int tid = threadIdx.x;
    const int ti = tid & 15, tj = tid >> 4;
    float acc[4][4];
    #pragma unroll
    for (int r=0;r<4;++r){ acc[r][0]=acc[r][1]=acc[r][2]=acc[r][3]=0.f; }

    for (int k0 = 0; k0 < K; k0 += 16) {
        __syncthreads();
        #pragma unroll
        for (int idx = tid; idx < 1024; idx += 256)
            As[idx>>4][idx&15] = A[(size_t)(m0 + (idx>>4))*K + k0 + (idx&15)];
        #pragma unroll
        for (int idx = tid; idx < 1024; idx += 256)
            Bs[idx>>6][idx&63] = B[(size_t)(k0 + (idx>>6))*N + n0 + (idx&63)];
        __syncthreads();
        #pragma unroll
        for (int kk = 0; kk < 16; ++kk) {
            float a0 = As[tj*4+0][kk], a1 = As[tj*4+1][kk],
                  a2 = As[tj*4+2][kk], a3 = As[tj*4+3][kk];
            float4 bv = *(const float4*)&Bs[kk][ti*4];
            acc[0][0]+=a0*bv.x; acc[0][1]+=a0*bv.y; acc[0][2]+=a0*bv.z; acc[0][3]+=a0*bv.w;
            acc[1][0]+=a1*bv.x; acc[1][1]+=a1*bv.y; acc[1][2]+=a1*bv.z; acc[1][3]+=a1*bv.w;
            acc[2][0]+=a2*bv.x; acc[2][1]+=a2*bv.y; acc[2][2]+=a2*bv.z; acc[2][3]+=a2*bv.w;
            acc[3][0]+=a3*bv.x; acc[3][1]+=a3*bv.y; acc[3][2]+=a3*bv.z; acc[3][3]+=a3*bv.w;
        }
    }
    #pragma unroll
    for (int r = 0; r < 4; ++r) {
        const size_t gi = (size_t)(m0 + tj*4 + r);
        #pragma unroll
        for (int c = 0; c < 4; ++c) {
            float v = acc[r][c];
            if (bias) v += bias[n0 + ti*4 + c];
            if (act == 1) v = lrelu(v);
            C[gi*N + n0 + ti*4 + c] = v;
        }
    }
}

// ---------------- src/dst score kernels ----------------
__global__ void k_srcdst1(const float* __restrict__ a_gat){
    const int row = blockIdx.x;            // b*512+n
    const int b = row >> 9, n = row & 511;
    const int tid = threadIdx.x;           // 256
    __shared__ float wrow[256];
    wrow[tid] = g_wh1[(size_t)row*256 + tid];
    __syncthreads();
    const int w = tid >> 5, l = tid & 31;
    const int h = w >> 1, half = w & 1;
    float v = wrow[h*64 + l]      * a_gat[h*128 + half*64 + l]
            + wrow[h*64 + 32 + l] * a_gat[h*128 + half*64 + 32 + l];
    #pragma unroll
    for (int o = 16; o; o >>= 1) v += __shfl_down_sync(0xffffffffu, v, o);
    if (l == 0) {
        float* out = half ? g_dst1 : g_src1;
        out[(size_t)(b*4 + h)*512 + n] = v;
    }
}

__global__ void k_srcdst2(const float* __restrict__ a_go){
    const int row = blockIdx.x;
    const int tid = threadIdx.x;           // 128
    __shared__ float wrow[128];
    __shared__ float part[4];
    wrow[tid] = g_wh2[(size_t)row*128 + tid];
    __syncthreads();
    const int w = tid >> 5, l = tid & 31;
    const int which = w >> 1, p = w & 1;
    float v = wrow[p*64 + l]      * a_go[which*128 + p*64 + l]
            + wrow[p*64 + 32 + l] * a_go[which*128 + p*64 + 32 + l];
    #pragma unroll
    for (int o = 16; o; o >>= 1) v += __shfl_down_sync(0xffffffffu, v, o);
    if (l == 0) part[w] = v;
    __syncthreads();
    if (tid == 0) g_src2[row] = part[0] + part[1];
    if (tid == 1) g_dst2[row] = part[2] + part[3];
}

// ---------------- fused GAT attention: softmax(rank-1 masked scores) @ Wh ----------------
// exp(leaky(s_i+d_j)) is separable => per-node exp tables; O(n) MUFU instead of O(n^2).
// grid: (512/64, H, B), block 256. Writes elu(hp) into out[.., h*64 .. h*64+F)
template<int F, int JT>
__global__ void __launch_bounds__(256) k_attn(
    const float* __restrict__ wh, const float* __restrict__ src,
    const float* __restrict__ dst, const int* __restrict__ adj,
    float* __restrict__ out, int WS, int H)
{
    const int it = blockIdx.x, h = blockIdx.y, b = blockIdx.z;
    const int i0 = it * 64;
    const int tid = threadIdx.x;
    const int whoff = h * 64;
    constexpr int FT = F / 16;

    __shared__ float D[512], P[512], Q[512];
    __shared__ float ssrc[64], sp[64], sq[64], Ssum[64];
    __shared__ float At[JT][68];
    __shared__ float Bs[JT][F + 4];
    __shared__ float pstmp[256];

    const float* dstb = dst + (size_t)(b*H + h) * 512;
    const float* srcb = src + (size_t)(b*H + h) * 512;

    for (int j = tid; j < 512; j += 256) {
        float d = dstb[j];
        D[j] = d; P[j] = __expf(d); Q[j] = __expf(0.2f*d);
    }
    if (tid < 64) {
        float s = srcb[i0 + tid];
        ssrc[tid] = s; sp[tid] = __expf(s); sq[tid] = __expf(0.2f*s);
        Ssum[tid] = 0.f;
    }
    __syncthreads();

    const int ti = tid & 15;
    const int tj = tid >> 4;
    float acc[4][FT];
    #pragma unroll
    for (int r = 0; r < 4; ++r)
        #pragma unroll
        for (int c = 0; c < FT; ++c) acc[r][c] = 0.f;

    const int ai  = tid >> 2;            // i in [0,64)
    constexpr int AJN = JT / 4;          // j's per thread
    const int aj0 = (tid & 3) * AJN;
    const float si  = ssrc[ai];
    const float pie = sp[ai], qie = sq[ai];

    constexpr int NJT = 512 / JT;
    for (int jt = 0; jt < NJT; ++jt) {
        const int j0 = jt * JT;
        __syncthreads();
        // load Wh tile
        for (int idx = tid; idx < JT * F / 4; idx += 256) {
            const int j  = idx / (F/4);
            const int f4 = (idx % (F/4)) * 4;
            const float4 v = *(const float4*)(wh + (size_t)(b*512 + j0 + j)*WS + whoff + f4);
            *(float4*)&Bs[j][f4] = v;
        }
        // build unnormalized attention tile (transposed) + partial row sums
        {
            const int* adjrow = adj + ((size_t)b*512 + (i0 + ai))*512 + j0 + aj0;
            float ps = 0.f;
            #pragma unroll
            for (int jj = 0; jj < AJN; ++jj) {
                float v = 0.f;
                if (adjrow[jj] > 0) {
                    const int j = j0 + aj0 + jj;
                    v = (si + D[j] > 0.f) ? pie * P[j] : qie * Q[j];
                }
                At[aj0 + jj][ai] = v;
                ps += v;
            }
            pstmp[tid] = ps;
        }
        __syncthreads();
        if (tid < 64)
            Ssum[tid] += pstmp[tid*4] + pstmp[tid*4+1] + pstmp[tid*4+2] + pstmp[tid*4+3];
        // GEMM: acc += At^T @ Bs
        #pragma unroll 4
        for (int k = 0; k < JT; ++k) {
            const float4 av = *(const float4*)&At[k][tj*4];
            const float a[4] = {av.x, av.y, av.z, av.w};
            #pragma unroll
            for (int c4 = 0; c4 < FT/4; ++c4) {
                const float4 bv = *(const float4*)&Bs[k][ti*FT + c4*4];
                #pragma unroll
                for (int r = 0; r < 4; ++r) {
                    acc[r][c4*4+0] += a[r]*bv.x;
                    acc[r][c4*4+1] += a[r]*bv.y;
                    acc[r][c4*4+2] += a[r]*bv.z;
                    acc[r][c4*4+3] += a[r]*bv.w;
                }
            }
        }
    }
    __syncthreads();
    #pragma unroll
    for (int r = 0; r < 4; ++r) {
        const int i = tj*4 + r;
        const float S = Ssum[i];
        const float inv = (S > 0.f) ? 1.f/S : 0.f;
        float* orow = out + ((size_t)(b*512) + i0 + i)*WS + whoff;
        #pragma unroll
        for (int c = 0; c < FT; ++c)
            orow[ti*FT + c] = eluf(acc[r][c] * inv);
    }
}

// ---------------- CNN ----------------
__global__ void k_conv1(const int* __restrict__ amino, const float* __restrict__ conv_b){
    const int l = blockIdx.x, b = blockIdx.y, f = threadIdx.x;
    float acc = conv_b[0];
    #pragma unroll
    for (int dl = 0; dl < 11; ++dl) {
        int l2 = l + dl - 5;
        if (l2 >= 0 && l2 < 1024) {
            int id = amino[b*1024 + l2];
            acc += g_T[((size_t)id*11 + dl)*128 + f];
        }
    }
    g_cnvA[((size_t)(b*1024) + l)*128 + f] = fmaxf(acc, 0.f);
}

// generic 11x11 SAME conv + bias + relu on (1024,128) image; sliding f-window
__global__ void __launch_bounds__(256) k_conv(
    const float* __restrict__ in, float* __restrict__ out,
    const float* __restrict__ wsrc, const float* __restrict__ bsrc)
{
    __shared__ float tile[26*139];
    __shared__ float ws[121];
    const int lb = blockIdx.x * 16, b = blockIdx.y;
    const int tid = threadIdx.x;
    if (tid < 121) ws[tid] = wsrc[tid];
    for (int idx = tid; idx < 26*138; idx += 256) {
        const int r = idx / 138, c = idx % 138;
        const int gl = lb + r - 5, gf = c - 5;
        float v = 0.f;
        if (gl >= 0 && gl < 1024 && gf >= 0 && gf < 128)
            v = in[((size_t)(b*1024) + gl)*128 + gf];
        tile[r*139 + c] = v;
    }
    __syncthreads();
    const int fg = tid >> 3, lg = tid & 7;
    const int f0 = fg * 4;
    const float bias = bsrc[0];
    float acc0[4] = {bias,bias,bias,bias};
    float acc1[4] = {bias,bias,bias,bias};
    for (int dl = 0; dl < 11; ++dl) {
        const float* w  = ws + dl*11;
        const float* r0 = tile + (lg + dl)*139 + f0;
        const float* r1 = r0 + 8*139;
        float v0[14], v1[14];
        #pragma unroll
        for (int j = 0; j < 14; ++j) { v0[j] = r0[j]; v1[j] = r1[j]; }
        #pragma unroll
        for (int df = 0; df < 11; ++df) {
            const float wv = w[df];
            #pragma unroll
            for (int k = 0; k < 4; ++k) {
                acc0[k] += wv * v0[df+k];
                acc1[k] += wv * v1[df+k];
            }
        }
    }
    float* o0 = out + ((size_t)(b*1024) + lb + lg)*128 + f0;
    float* o1 = o0 + 8*128;
    #pragma unroll
    for (int k = 0; k < 4; ++k) {
        o0[k] = fmaxf(acc0[k], 0.f);
        o1[k] = fmaxf(acc1[k], 0.f);
    }
}

// ---------------- masked mean pooling ----------------
__global__ void k_mean(const float* __restrict__ in, const float* __restrict__ mask,
                       float* __restrict__ outp, int NNd){
    const int b = blockIdx.x, f = threadIdx.x;   // 128 threads
    float s = 0.f, m = 0.f;
    for (int n = 0; n < NNd; ++n) {
        float mk = mask[b*NNd + n];
        m += mk;
        s += mk * in[((size_t)b*NNd + n)*128 + f];
    }
    outp[b*128 + f] = s / m;
}

// ---------------- final predictor ----------------
__global__ void k_final(const float* __restrict__ pred_w, const float* __restrict__ pred_b,
                        float* __restrict__ out){
    __shared__ float red[256];
    const int b = blockIdx.x, c = threadIdx.x;
    float v = (c < 128) ? g_comp[b*128 + c] : g_prot[b*128 + (c - 128)];
    v = v > 0.f ? v : 0.04f*v;     // leaky_relu applied twice
    red[c] = v * pred_w[c];
    __syncthreads();
    for (int s = 128; s > 0; s >>= 1) {
        if (c < s) red[c] += red[c + s];
        __syncthreads();
    }
    if (c == 0) out[b] = red[0] + pred_b[0];
}

// ---------------- launch ----------------
extern "C" void kernel_launch(void* const* d_in, const int* in_sizes, int n_in,
                              void* d_out, int out_size)
{
    const int*   atoms      = (const int*)  d_in[0];
    const float* atoms_mask = (const float*)d_in[1];
    const int*   adj        = (const int*)  d_in[2];
    const int*   amino      = (const int*)  d_in[3];
    const float* amino_mask = (const float*)d_in[4];
    const float* E_atom     = (const float*)d_in[5];
    const float* E_amino    = (const float*)d_in[6];
    const float* W_gat      = (const float*)d_in[7];
    const float* a_gat      = (const float*)d_in[8];
    const float* W_go       = (const float*)d_in[9];
    const float* a_go       = (const float*)d_in[10];
    const float* W_comp_w   = (const float*)d_in[11];
    const float* W_comp_b   = (const float*)d_in[12];
    const float* conv_w     = (const float*)d_in[13];
    const float* conv_b     = (const float*)d_in[14];
    const float* W_att_w    = (const float*)d_in[15];
    const float* W_att_b    = (const float*)d_in[16];
    const float* pred_w     = (const float*)d_in[17];
    const float* pred_b     = (const float*)d_in[18];
    float* out = (float*)d_out;

    float *p_Wcat, *p_WcompT, *p_WattT;
    float *p_av, *p_wh1, *p_multi, *p_wh2, *p_x, *p_atoms_vec, *p_av_att;
    float *p_src1, *p_dst1, *p_src2, *p_dst2, *p_cnvA, *p_cnvB, *p_comp, *p_prot;
    cudaGetSymbolAddress((void**)&p_Wcat,   g_Wcat);
    cudaGetSymbolAddress((void**)&p_WcompT, g_WcompT);
    cudaGetSymbolAddress((void**)&p_WattT,  g_WattT);
    cudaGetSymbolAddress((void**)&p_av,     g_av);
    cudaGetSymbolAddress((void**)&p_wh1,    g_wh1);
    cudaGetSymbolAddress((void**)&p_multi,  g_multi);
    cudaGetSymbolAddress((void**)&p_wh2,    g_wh2);
    cudaGetSymbolAddress((void**)&p_x,      g_x);
    cudaGetSymbolAddress((void**)&p_atoms_vec, g_atoms_vec);
    cudaGetSymbolAddress((void**)&p_av_att, g_av_att);
    cudaGetSymbolAddress((void**)&p_src1,   g_src1);
    cudaGetSymbolAddress((void**)&p_dst1,   g_dst1);
    cudaGetSymbolAddress((void**)&p_src2,   g_src2);
    cudaGetSymbolAddress((void**)&p_dst2,   g_dst2);
    cudaGetSymbolAddress((void**)&p_cnvA,   g_cnvA);
    cudaGetSymbolAddress((void**)&p_cnvB,   g_cnvB);
    cudaGetSymbolAddress((void**)&p_comp,   g_comp);
    cudaGetSymbolAddress((void**)&p_prot,   g_prot);

    // weight prep
    k_pack_wgat<<<128, 256>>>(W_gat);
    k_transp128<<<128, 128>>>(W_comp_w, p_WcompT);
    k_transp128<<<128, 128>>>(W_att_w,  p_WattT);
    k_table<<<dim3(11, 30), 128>>>(conv_w, E_amino);

    // ---- compound branch ----
    k_embed_atoms<<<BB*NN_, 128>>>(atoms, E_atom);
    k_gemm<<<dim3(128, 4), 256>>>(p_av, p_Wcat, nullptr, p_wh1, 8192, 256, 128, 0);
    k_srcdst1<<<BB*NN_, 256>>>(a_gat);
    k_attn<64, 64><<<dim3(8, 4, BB), 256>>>(p_wh1, p_src1, p_dst1, adj, p_multi, 256, 4);
    k_gemm<<<dim3(128, 2), 256>>>(p_multi, W_go, nullptr, p_wh2, 8192, 128, 256, 0);
    k_srcdst2<<<BB*NN_, 128>>>(a_go);
    k_attn<128, 32><<<dim3(8, 1, BB), 256>>>(p_wh2, p_src2, p_dst2, adj, p_x, 128, 1);
    k_gemm<<<dim3(128, 2), 256>>>(p_x, p_WcompT, W_comp_b, p_atoms_vec, 8192, 128, 128, 1);
    k_gemm<<<dim3(128, 2), 256>>>(p_atoms_vec, p_WattT, W_att_b, p_av_att, 8192, 128, 128, 1);
    k_mean<<<BB, 128>>>(p_av_att, atoms_mask, p_comp, NN_);

    // ---- protein branch ----
    k_conv1<<<dim3(LL, BB), 128>>>(amino, conv_b);
    k_conv<<<dim3(64, BB), 256>>>(p_cnvA, p_cnvB, conv_w + 121,   conv_b + 1);
    k_conv<<<dim3(64, BB), 256>>>(p_cnvB, p_cnvA, conv_w + 2*121, conv_b + 2);
    k_gemm<<<dim3(256, 2), 256>>>(p_cnvA, p_WattT, W_att_b, p_cnvB, 16384, 128, 128, 1);
    k_mean<<<BB, 128>>>(p_cnvB, amino_mask, p_prot, LL);

    // ---- head ----
    k_final<<<BB, 256>>>(pred_w, pred_b, out);
}